// round 6
// baseline (speedup 1.0000x reference)
#include <cuda_runtime.h>
#include <cuda_bf16.h>
#include <cstdint>
#include <math.h>

#define DM     512
#define BATCH  256
#define WIN    256
#define ENC    55
#define LATENT 128
#define BS     (BATCH * DM)

// ---------------- global scratch ----------------
__device__ float g_hs[(WIN + 1) * BS];            // fp32 hidden history
__device__ signed char g_hhi8[2][BS];             // h int8 split hi (ping-pong)
__device__ signed char g_hlo8[2][BS];             // h int8 split lo
__device__ signed char g_whi8[3 * DM * DM];       // W int8 split hi
__device__ signed char g_wlo8[3 * DM * DM];       // W int8 split lo
__device__ unsigned g_bar8[8];                    // per-group arrival counters
__device__ volatile unsigned g_flag8[8];          // per-group release flags

// ---------------- PTX helpers ----------------
__device__ __forceinline__ uint32_t smem_u32(const void* p) {
    uint32_t a;
    asm("{ .reg .u64 t; cvta.to.shared.u64 t, %1; cvt.u32.u64 %0, t; }" : "=r"(a) : "l"(p));
    return a;
}
__device__ __forceinline__ void cp16(uint32_t dst, const void* src) {
    asm volatile("cp.async.cg.shared.global [%0], [%1], 16;" :: "r"(dst), "l"(src));
}
#define CP_COMMIT() asm volatile("cp.async.commit_group;" ::: "memory")
template <int N> __device__ __forceinline__ void cp_wait() {
    asm volatile("cp.async.wait_group %0;" :: "n"(N) : "memory");
}
__device__ __forceinline__ void ldsm_x4(uint32_t r[4], uint32_t addr) {
    asm volatile("ldmatrix.sync.aligned.m8n8.x4.shared.b16 {%0,%1,%2,%3}, [%4];"
                 : "=r"(r[0]), "=r"(r[1]), "=r"(r[2]), "=r"(r[3]) : "r"(addr));
}
__device__ __forceinline__ void ldsm_x2(uint32_t r[2], uint32_t addr) {
    asm volatile("ldmatrix.sync.aligned.m8n8.x2.shared.b16 {%0,%1}, [%2];"
                 : "=r"(r[0]), "=r"(r[1]) : "r"(addr));
}
__device__ __forceinline__ void mma_s8(int c[4], const uint32_t a[4], const uint32_t b[2]) {
    asm volatile("mma.sync.aligned.m16n8k32.row.col.s32.s8.s8.s32 "
                 "{%0,%1,%2,%3}, {%4,%5,%6,%7}, {%8,%9}, {%0,%1,%2,%3};"
                 : "+r"(c[0]), "+r"(c[1]), "+r"(c[2]), "+r"(c[3])
                 : "r"(a[0]), "r"(a[1]), "r"(a[2]), "r"(a[3]), "r"(b[0]), "r"(b[1]));
}

// ---------------- persistent kernel config ----------------
#define NCTA     256
#define UT       16                   // units per CTA (N = 48 with 3 gates)
#define MT       32                   // batch rows per CTA
#define NGRP     8                    // 8 independent batch groups (32 rows each)
#define GSZ      32                   // CTAs per group
#define WROW_B   528                  // W smem row stride (512 data + 16 pad)
#define AROW_B   272                  // A smem row stride (256 data + 16 pad)
#define KCB      256                  // K chunk bytes (elems)
#define WHI_OFF  0
#define WLO_OFF  25344                // 48*528
#define A_OFF    50688
#define A_STAGE  17408                // (32*272) * 2 (hi+lo)
#define A_HALF   8704
#define DYN_BYTES (A_OFF + 2 * A_STAGE)   // 85504
#define GEX_STRIDE 52

__device__ __forceinline__ void loadA(uint32_t dstHi,
                                      const signed char* __restrict__ hi,
                                      const signed char* __restrict__ lo,
                                      int b0, int kc, int tid) {
#pragma unroll
    for (int p = 0; p < 4; p++) {
        int idx = tid + 128 * p;          // 0..511
        int row = idx >> 4, c16 = idx & 15;
        cp16(dstHi + row * AROW_B + c16 * 16,
             hi + (size_t)(b0 + row) * DM + kc + c16 * 16);
    }
#pragma unroll
    for (int p = 0; p < 4; p++) {
        int idx = tid + 128 * p;
        int row = idx >> 4, c16 = idx & 15;
        cp16(dstHi + A_HALF + row * AROW_B + c16 * 16,
             lo + (size_t)(b0 + row) * DM + kc + c16 * 16);
    }
}

__global__ void __launch_bounds__(128, 2)
gru_persistent(const float* __restrict__ b_ih, const float* __restrict__ b_hh) {
    extern __shared__ char dyn[];
    __shared__ float gex[MT * GEX_STRIDE];
    __shared__ float s_sr[UT], s_sz[UT], s_bin[UT], s_bhn[UT];

    const int tid = threadIdx.x;
    const int lane = tid & 31;
    const int warp = tid >> 5;
    const int m_base = (warp >> 1) * 16;   // 2 M-tiles of 16 rows
    const int n_base = (warp & 1) * 24;    // 2 N-tiles of 24 cols
    const int cta = blockIdx.x;
    const int u0 = (cta & 31) * UT;
    const int grp = cta >> 5;              // batch group 0..7
    const int b0 = grp * MT;
    const uint32_t sb = smem_u32(dyn);

    // ---- resident int8 weight tiles (once) ----
    for (int idx = tid; idx < 48 * 32; idx += 128) {
        int row = idx >> 5, c = idx & 31;
        int gr = (row >> 4) * DM + u0 + (row & 15);
        *reinterpret_cast<uint4*>(dyn + WHI_OFF + row * WROW_B + c * 16) =
            *reinterpret_cast<const uint4*>(g_whi8 + (size_t)gr * DM + c * 16);
        *reinterpret_cast<uint4*>(dyn + WLO_OFF + row * WROW_B + c * 16) =
            *reinterpret_cast<const uint4*>(g_wlo8 + (size_t)gr * DM + c * 16);
    }
    if (tid < UT) {
        int j = u0 + tid;
        s_sr[tid]  = b_ih[j] + b_hh[j];
        s_sz[tid]  = b_ih[DM + j] + b_hh[DM + j];
        s_bin[tid] = b_ih[2 * DM + j];
        s_bhn[tid] = b_hh[2 * DM + j];
    }
    __syncthreads();

    const uint32_t a_off = (uint32_t)(((lane & 7) + ((lane >> 3) & 1) * 8) * AROW_B
                                      + ((lane >> 4) & 1) * 16);
    const uint32_t b_off = (uint32_t)((n_base + (lane & 7)) * WROW_B
                                      + ((lane >> 3) & 1) * 16);
    const uint32_t wh_base = sb + WHI_OFF + b_off;
    const uint32_t wl_base = sb + WLO_OFF + b_off;

    for (int t = 0; t < WIN; t++) {
        const signed char* __restrict__ hsel = g_hhi8[t & 1];
        const signed char* __restrict__ lsel = g_hlo8[t & 1];

        loadA(sb + A_OFF, hsel, lsel, b0, 0, tid);
        CP_COMMIT();
        loadA(sb + A_OFF + A_STAGE, hsel, lsel, b0, KCB, tid);
        CP_COMMIT();

        int acc1[3][4], acc2[3][4];
#pragma unroll
        for (int ni = 0; ni < 3; ni++)
#pragma unroll
            for (int q = 0; q < 4; q++) { acc1[ni][q] = 0; acc2[ni][q] = 0; }

#pragma unroll
        for (int ch = 0; ch < 2; ch++) {
            if (ch == 0) cp_wait<1>(); else cp_wait<0>();
            __syncthreads();
            const uint32_t ah_base = sb + A_OFF + ch * A_STAGE + m_base * AROW_B + a_off;
            const uint32_t al_base = ah_base + A_HALF;
#pragma unroll
            for (int k = 0; k < 8; k++) {
                uint32_t ah[4], al[4];
                ldsm_x4(ah, ah_base + k * 32);
                ldsm_x4(al, al_base + k * 32);
                const uint32_t kb = (uint32_t)(ch * KCB + k * 32);
                uint32_t bh[3][2], bl[3][2];
#pragma unroll
                for (int ni = 0; ni < 3; ni++) {
                    ldsm_x2(bh[ni], wh_base + ni * 8 * WROW_B + kb);
                    ldsm_x2(bl[ni], wl_base + ni * 8 * WROW_B + kb);
                }
#pragma unroll
                for (int ni = 0; ni < 3; ni++) {
                    mma_s8(acc1[ni], ah, bh[ni]);
                    mma_s8(acc2[ni], ah, bl[ni]);
                    mma_s8(acc2[ni], al, bh[ni]);
                }
            }
        }

        // gh = acc1*2^-14 + acc2*2^-22 ; exchange through smem
#pragma unroll
        for (int ni = 0; ni < 3; ni++) {
            int r0 = m_base + (lane >> 2);
            int c0 = n_base + ni * 8 + (lane & 3) * 2;
            float v0 = (float)acc1[ni][0] * 6.103515625e-5f + (float)acc2[ni][0] * 2.384185791015625e-7f;
            float v1 = (float)acc1[ni][1] * 6.103515625e-5f + (float)acc2[ni][1] * 2.384185791015625e-7f;
            float v2 = (float)acc1[ni][2] * 6.103515625e-5f + (float)acc2[ni][2] * 2.384185791015625e-7f;
            float v3 = (float)acc1[ni][3] * 6.103515625e-5f + (float)acc2[ni][3] * 2.384185791015625e-7f;
            *reinterpret_cast<float2*>(&gex[r0 * GEX_STRIDE + c0]) = make_float2(v0, v1);
            *reinterpret_cast<float2*>(&gex[(r0 + 8) * GEX_STRIDE + c0]) = make_float2(v2, v3);
        }
        __syncthreads();

        {
            const int b_l = tid >> 2;           // 0..31
            const int uh = (tid & 3) * 4;       // 4 units each
            const int b = b0 + b_l;
            const float* __restrict__ hp = g_hs + (size_t)t * BS + (size_t)b * DM + u0 + uh;
            float* __restrict__ hn = g_hs + (size_t)(t + 1) * BS + (size_t)b * DM + u0 + uh;
            signed char* __restrict__ oh = g_hhi8[(t + 1) & 1] + (size_t)b * DM + u0 + uh;
            signed char* __restrict__ ol = g_hlo8[(t + 1) & 1] + (size_t)b * DM + u0 + uh;
#pragma unroll
            for (int uu = 0; uu < 4; uu++) {
                int u = uh + uu;
                float gr = gex[b_l * GEX_STRIDE + u];
                float gz = gex[b_l * GEX_STRIDE + 16 + u];
                float gn = gex[b_l * GEX_STRIDE + 32 + u];
                float r  = 1.f / (1.f + expf(-(s_sr[u] + gr)));
                float zg = 1.f / (1.f + expf(-(s_sz[u] + gz)));
                float n  = tanhf(s_bin[u] + r * (s_bhn[u] + gn));
                float h  = (1.f - zg) * n + zg * hp[uu];
                hn[uu] = h;
                int v16 = __float2int_rn(h * 16384.f);
                int hi = (v16 + 128) >> 8;
                ol[uu] = (signed char)(v16 - (hi << 8));
                oh[uu] = (signed char)hi;
            }
        }
        __threadfence();
        __syncthreads();

        // ---- group-local barrier (32 CTAs of this batch group) ----
        if (tid == 0) {
            const unsigned tgt = (unsigned)(t + 1);
            unsigned old = atomicAdd(&g_bar8[grp], 1u);
            if (old == (unsigned)GSZ * tgt - 1u) {
                __threadfence();
                g_flag8[grp] = tgt;
            } else {
                while (g_flag8[grp] < tgt) { }
            }
        }
        __syncthreads();
    }
}

// ---------------- weight int8 split prep ----------------
__global__ void prep_kernel(const float* __restrict__ w) {
    int i = blockIdx.x * blockDim.x + threadIdx.x;
    if (i < 3 * DM * DM) {
        int w16 = __float2int_rn(w[i] * 65536.f);
        w16 = max(-32511, min(32511, w16));
        int hi = (w16 + 128) >> 8;
        g_whi8[i] = (signed char)hi;
        g_wlo8[i] = (signed char)(w16 - (hi << 8));
    }
}

// ---------------- h0 ----------------
__global__ void h0_kernel(const float* __restrict__ z,
                          const float* __restrict__ w,
                          const float* __restrict__ bias) {
    __shared__ float zs[LATENT];
    const int b = blockIdx.x;
    const int j = threadIdx.x;
    if (b == 0 && j < 8) { g_bar8[j] = 0; g_flag8[j] = 0; }   // reset per replay
    if (threadIdx.x < LATENT) zs[threadIdx.x] = z[b * LATENT + threadIdx.x];
    __syncthreads();
    float acc = 0.f;
    const float4* wr = reinterpret_cast<const float4*>(w + (size_t)j * LATENT);
#pragma unroll
    for (int k4 = 0; k4 < LATENT / 4; k4++) {
        float4 w4 = __ldg(&wr[k4]);
        acc += zs[4 * k4 + 0] * w4.x + zs[4 * k4 + 1] * w4.y
             + zs[4 * k4 + 2] * w4.z + zs[4 * k4 + 3] * w4.w;
    }
    float h = tanhf(acc + bias[j]);
    g_hs[(size_t)b * DM + j] = h;
    int v16 = __float2int_rn(h * 16384.f);
    int hi = (v16 + 128) >> 8;
    g_hhi8[0][(size_t)b * DM + j] = (signed char)hi;
    g_hlo8[0][(size_t)b * DM + j] = (signed char)(v16 - (hi << 8));
}

// ---------------- output GEMM: 128x64 tile, 8x4 per thread ----------------
#define OKC 32
__global__ void __launch_bounds__(256)
out_kernel(const float* __restrict__ out_w,
           const float* __restrict__ out_b,
           float* __restrict__ out) {
    __shared__ float shH[OKC][132];
    __shared__ float shW[OKC][68];
    const int R0  = blockIdx.x * 128;
    const int tid = threadIdx.x;
    const int tx  = tid & 15;
    const int ty  = tid >> 4;
    const float* __restrict__ hsrc = g_hs + (size_t)BS;

    float acc[8][4] = {};
    for (int k0 = 0; k0 < DM; k0 += OKC) {
#pragma unroll
        for (int p = 0; p < 4; p++) {
            int idx = tid + 256 * p;
            int row = idx >> 3;
            int c4  = (idx & 7) * 4;
            float4 v = *reinterpret_cast<const float4*>(
                &hsrc[(size_t)(R0 + row) * DM + k0 + c4]);
            shH[c4 + 0][row] = v.x; shH[c4 + 1][row] = v.y;
            shH[c4 + 2][row] = v.z; shH[c4 + 3][row] = v.w;
        }
#pragma unroll
        for (int p = 0; p < 2; p++) {
            int idx = tid + 256 * p;
            int i   = idx >> 3;
            int c4  = (idx & 7) * 4;
            float4 v = make_float4(0.f, 0.f, 0.f, 0.f);
            if (i < ENC)
                v = *reinterpret_cast<const float4*>(&out_w[(size_t)i * DM + k0 + c4]);
            shW[c4 + 0][i] = v.x; shW[c4 + 1][i] = v.y;
            shW[c4 + 2][i] = v.z; shW[c4 + 3][i] = v.w;
        }
        __syncthreads();
#pragma unroll
        for (int kk = 0; kk < OKC; kk++) {
            float4 h0 = *reinterpret_cast<const float4*>(&shH[kk][ty * 8]);
            float4 h1 = *reinterpret_cast<const float4*>(&shH[kk][ty * 8 + 4]);
            float4 wv = *reinterpret_cast<const float4*>(&shW[kk][tx * 4]);
            float h[8] = {h0.x, h0.y, h0.z, h0.w, h1.x, h1.y, h1.z, h1.w};
            float w[4] = {wv.x, wv.y, wv.z, wv.w};
#pragma unroll
            for (int rr = 0; rr < 8; rr++)
#pragma unroll
                for (int cc = 0; cc < 4; cc++)
                    acc[rr][cc] += h[rr] * w[cc];
        }
        __syncthreads();
    }
#pragma unroll
    for (int rr = 0; rr < 8; rr++) {
        int R  = R0 + ty * 8 + rr;
        int tt = R >> 8;
        int b  = R & 255;
#pragma unroll
        for (int cc = 0; cc < 4; cc++) {
            int i = tx * 4 + cc;
            if (i < ENC)
                out[((size_t)b * WIN + tt) * ENC + i] = acc[rr][cc] + __ldg(&out_b[i]);
        }
    }
}

// ---------------- launch ----------------
extern "C" void kernel_launch(void* const* d_in, const int* in_sizes, int n_in,
                              void* d_out, int out_size) {
    (void)in_sizes; (void)n_in; (void)out_size;
    const float* z        = (const float*)d_in[0];
    const float* h_proj_w = (const float*)d_in[1];
    const float* h_proj_b = (const float*)d_in[2];
    const float* w_hh     = (const float*)d_in[4];
    const float* b_ih     = (const float*)d_in[5];
    const float* b_hh     = (const float*)d_in[6];
    const float* out_w    = (const float*)d_in[7];
    const float* out_b    = (const float*)d_in[8];
    float* out = (float*)d_out;

    static bool attr_done = false;
    if (!attr_done) {
        cudaFuncSetAttribute(gru_persistent,
                             cudaFuncAttributeMaxDynamicSharedMemorySize, DYN_BYTES);
        attr_done = true;
    }

    prep_kernel<<<(3 * DM * DM + 255) / 256, 256>>>(w_hh);
    h0_kernel<<<BATCH, DM>>>(z, h_proj_w, h_proj_b);
    gru_persistent<<<NCTA, 128, DYN_BYTES>>>(b_ih, b_hh);
    out_kernel<<<(WIN * BATCH) / 128, 256>>>(out_w, out_b, out);
}

// round 7
// speedup vs baseline: 1.7865x; 1.7865x over previous
#include <cuda_runtime.h>
#include <cuda_bf16.h>
#include <cstdint>
#include <math.h>

#define DM     512
#define BATCH  256
#define WIN    256
#define ENC    55
#define LATENT 128
#define BS     (BATCH * DM)

// ---------------- global scratch ----------------
__device__ float g_hs[(WIN + 1) * BS];            // fp32 hidden history (normal layout)
// h split arrays, SWIZZLED tile layout: 4 tiles (batch groups of 64) x 64KB.
// elem offset(b,u) = (b>>6)*32768 + (b&63)*512 + (((u>>3) ^ (b&7))<<3) + (u&7)
__device__ __nv_bfloat16 g_hhi[2][BS];
__device__ __nv_bfloat16 g_hlo[2][BS];
__device__ __nv_bfloat16 g_whi[3 * DM * DM];      // W split hi (normal layout)
__device__ __nv_bfloat16 g_wlo[3 * DM * DM];      // W split lo
__device__ unsigned g_bar4[4];                    // per-group arrival counters
__device__ volatile unsigned g_flag4[4];          // per-group release flags

// ---------------- PTX helpers ----------------
__device__ __forceinline__ uint32_t smem_u32(const void* p) {
    uint32_t a;
    asm("{ .reg .u64 t; cvta.to.shared.u64 t, %1; cvt.u32.u64 %0, t; }" : "=r"(a) : "l"(p));
    return a;
}
__device__ __forceinline__ void bulkcp(uint32_t dst, const void* src, uint32_t bytes,
                                       uint32_t mbar) {
    asm volatile("cp.async.bulk.shared::cluster.global.mbarrier::complete_tx::bytes "
                 "[%0], [%1], %2, [%3];"
                 :: "r"(dst), "l"(src), "r"(bytes), "r"(mbar) : "memory");
}
#define MBAR_INIT(a, c) asm volatile("mbarrier.init.shared.b64 [%0], %1;" :: "r"(a), "r"(c) : "memory")
#define MBAR_EXPECT(a, bytes) \
    asm volatile("mbarrier.arrive.expect_tx.shared.b64 _, [%0], %1;" :: "r"(a), "r"(bytes) : "memory")
#define MBAR_WAIT(a, par) do {                                                              \
    uint32_t _m = (a), _p = (par), _d;                                                      \
    asm volatile("{ .reg .pred p; mbarrier.try_wait.parity.acquire.cta.shared::cta.b64 p, [%1], %2; selp.b32 %0,1,0,p; }" \
                 : "=r"(_d) : "r"(_m), "r"(_p) : "memory");                                 \
    if (!_d) {                                                                              \
        asm volatile("{ .reg .pred P1; WL%=: mbarrier.try_wait.parity.acquire.cta.shared::cta.b64 P1, [%0], %1, 0x989680; @P1 bra.uni WD%=; bra.uni WL%=; WD%=: }" \
                     :: "r"(_m), "r"(_p) : "memory");                                       \
    }                                                                                       \
} while (0)
#define FENCE_ASYNC()  asm volatile("fence.proxy.async;" ::: "memory")
#define FENCE_GPU()    asm volatile("fence.acq_rel.gpu;" ::: "memory")

__device__ __forceinline__ void ldsm_x4(uint32_t r[4], uint32_t addr) {
    asm volatile("ldmatrix.sync.aligned.m8n8.x4.shared.b16 {%0,%1,%2,%3}, [%4];"
                 : "=r"(r[0]), "=r"(r[1]), "=r"(r[2]), "=r"(r[3]) : "r"(addr));
}
__device__ __forceinline__ void ldsm_x2(uint32_t r[2], uint32_t addr) {
    asm volatile("ldmatrix.sync.aligned.m8n8.x2.shared.b16 {%0,%1}, [%2];"
                 : "=r"(r[0]), "=r"(r[1]) : "r"(addr));
}
__device__ __forceinline__ void mma_bf16(float c[4], const uint32_t a[4], const uint32_t b[2]) {
    asm volatile("mma.sync.aligned.m16n8k16.row.col.f32.bf16.bf16.f32 "
                 "{%0,%1,%2,%3}, {%4,%5,%6,%7}, {%8,%9}, {%0,%1,%2,%3};"
                 : "+f"(c[0]), "+f"(c[1]), "+f"(c[2]), "+f"(c[3])
                 : "r"(a[0]), "r"(a[1]), "r"(a[2]), "r"(a[3]), "r"(b[0]), "r"(b[1]));
}

// ---------------- persistent kernel config ----------------
#define NCTA    128
#define UT      16                    // units per CTA (N = 48)
#define MT      64                    // batch rows per CTA
#define GSZ     32                    // CTAs per batch group
// dyn smem layout (bytes):
#define WS_HI   0                     // 48 rows x 1024B, swizzled
#define WS_LO   49152
#define AS_HI   98304                 // 64 rows x 1024B, 4 chunks of 16384
#define AS_LO   163840
#define DYN_BYTES 229376
#define CHUNK_B 16384
#define GEXROW_B 208                  // 52 floats per gex row

// split h-element offset (swizzled tiles)
__device__ __forceinline__ int hsplit_off(int b, int u) {
    int r = b & 63;
    return ((b >> 6) << 15) + (r << 9) + ((((u >> 3) ^ (r & 7))) << 3) + (u & 7);
}

__global__ void __launch_bounds__(256, 1)
gru_persistent(const float* __restrict__ b_ih, const float* __restrict__ b_hh) {
    extern __shared__ char dyn[];
    __shared__ __align__(16) uint64_t s_mbar[4];
    __shared__ float s_sr[UT], s_sz[UT], s_bin[UT], s_bhn[UT];

    const int tid = threadIdx.x;
    const int lane = tid & 31;
    const int warp = tid >> 5;
    const int chunk = warp >> 1;          // warp-pair's M chunk (16 rows)
    const int m_base = chunk * 16;
    const int n_base = (warp & 1) * 24;
    const int cta = blockIdx.x;
    const int u0 = (cta & 31) * UT;
    const int grp = cta >> 5;             // batch group 0..3
    const int gb0 = grp * MT;
    const uint32_t sb = smem_u32(dyn);

    // ---- resident W tiles, swizzled stores (once) ----
    for (int idx = tid; idx < 48 * 64; idx += 256) {
        int row = idx >> 6, g = idx & 63;
        int gr = (row >> 4) * DM + u0 + (row & 15);
        int sg = g ^ (row & 7);
        *reinterpret_cast<uint4*>(dyn + WS_HI + row * 1024 + sg * 16) =
            *reinterpret_cast<const uint4*>(g_whi + (size_t)gr * DM + g * 8);
        *reinterpret_cast<uint4*>(dyn + WS_LO + row * 1024 + sg * 16) =
            *reinterpret_cast<const uint4*>(g_wlo + (size_t)gr * DM + g * 8);
    }
    if (tid < UT) {
        int j = u0 + tid;
        s_sr[tid]  = b_ih[j] + b_hh[j];
        s_sz[tid]  = b_ih[DM + j] + b_hh[DM + j];
        s_bin[tid] = b_ih[2 * DM + j];
        s_bhn[tid] = b_hh[2 * DM + j];
    }
    if (tid == 0) {
        uint32_t mb = smem_u32(s_mbar);
#pragma unroll
        for (int i = 0; i < 4; i++) MBAR_INIT(mb + 8 * i, 1);
        FENCE_ASYNC();
    }
    __syncthreads();
    const uint32_t mb0 = smem_u32(s_mbar);

    // per-lane fragment addressing (swizzle-aware)
    const int arow = (lane & 7) + ((lane >> 3) & 1) * 8;     // 0..15 within chunk
    const uint32_t aRowHi = sb + AS_HI + (uint32_t)chunk * CHUNK_B + arow * 1024;
    const int sA = arow & 7;
    const int aHalf = (lane >> 4) & 1;
    const int wrow0 = n_base + (lane & 7);                   // + ni*8
    const int sW = lane & 7;
    const int wHalf = (lane >> 3) & 1;
    const uint32_t wHiBase = sb + WS_HI + wrow0 * 1024;
    const uint32_t wLoBase = sb + WS_LO + wrow0 * 1024;

    for (int t = 0; t < WIN; t++) {
        // ---- issue bulk copies for this step's A tile ----
        if (tid == 0) {
            FENCE_ASYNC();
            const __nv_bfloat16* srcH = g_hhi[t & 1] + (grp << 15);
            const __nv_bfloat16* srcL = g_hlo[t & 1] + (grp << 15);
#pragma unroll
            for (int c = 0; c < 4; c++) MBAR_EXPECT(mb0 + 8 * c, 2 * CHUNK_B);
#pragma unroll
            for (int c = 0; c < 4; c++) {
                bulkcp(sb + AS_HI + c * CHUNK_B, srcH + c * 8192, CHUNK_B, mb0 + 8 * c);
                bulkcp(sb + AS_LO + c * CHUNK_B, srcL + c * 8192, CHUNK_B, mb0 + 8 * c);
            }
        }

        float cf[3][4];
#pragma unroll
        for (int ni = 0; ni < 3; ni++)
#pragma unroll
            for (int q = 0; q < 4; q++) cf[ni][q] = 0.f;

        MBAR_WAIT(mb0 + 8 * chunk, t & 1);

#pragma unroll 4
        for (int k16 = 0; k16 < 32; k16++) {
            const int cA = k16 * 2 + aHalf;
            const uint32_t aHiAddr = aRowHi + (uint32_t)((cA ^ sA) << 4);
            uint32_t ah[4], al[4];
            ldsm_x4(ah, aHiAddr);
            ldsm_x4(al, aHiAddr + (AS_LO - AS_HI));
            const int cW = k16 * 2 + wHalf;
            const uint32_t wOff = (uint32_t)((cW ^ sW) << 4);
            uint32_t bh[3][2], bl[3][2];
#pragma unroll
            for (int ni = 0; ni < 3; ni++) {
                ldsm_x2(bh[ni], wHiBase + ni * 8192 + wOff);
                ldsm_x2(bl[ni], wLoBase + ni * 8192 + wOff);
            }
#pragma unroll
            for (int ni = 0; ni < 3; ni++) {
                mma_bf16(cf[ni], ah, bh[ni]);
                mma_bf16(cf[ni], ah, bl[ni]);
                mma_bf16(cf[ni], al, bh[ni]);
            }
        }

        // pair-level sync: both warps of this chunk done reading A before gex overlay
        asm volatile("bar.sync %0, 64;" :: "r"(chunk + 1) : "memory");

        // gex overlays A-hi chunk region: row r (global 0..63) ->
        //   dyn + AS_HI + (r>>4)*CHUNK_B + (r&15)*GEXROW_B
#pragma unroll
        for (int ni = 0; ni < 3; ni++) {
            int rl = lane >> 2;                       // row within chunk (0..7)
            int c0 = n_base + ni * 8 + (lane & 3) * 2;
            char* base = dyn + AS_HI + chunk * CHUNK_B;
            *reinterpret_cast<float2*>(base + rl * GEXROW_B + c0 * 4) =
                make_float2(cf[ni][0], cf[ni][1]);
            *reinterpret_cast<float2*>(base + (rl + 8) * GEXROW_B + c0 * 4) =
                make_float2(cf[ni][2], cf[ni][3]);
        }
        __syncthreads();

        // ---- gate epilogue: thread = batch row, 4 units ----
        {
            const int b_l = tid >> 2;                 // 0..63
            const int uh = (tid & 3) * 4;
            const int b = gb0 + b_l;
            const float* gexrow = reinterpret_cast<const float*>(
                dyn + AS_HI + (b_l >> 4) * CHUNK_B + (b_l & 15) * GEXROW_B);
            const float* __restrict__ hp = g_hs + (size_t)t * BS + (size_t)b * DM + u0 + uh;
            float* __restrict__ hn = g_hs + (size_t)(t + 1) * BS + (size_t)b * DM + u0 + uh;
            __nv_bfloat16 vh[4], vl[4];
#pragma unroll
            for (int uu = 0; uu < 4; uu++) {
                int u = uh + uu;
                float gr = gexrow[u];
                float gz = gexrow[16 + u];
                float gn = gexrow[32 + u];
                float r  = 1.f / (1.f + expf(-(s_sr[u] + gr)));
                float zg = 1.f / (1.f + expf(-(s_sz[u] + gz)));
                float n  = tanhf(s_bin[u] + r * (s_bhn[u] + gn));
                float h  = (1.f - zg) * n + zg * hp[uu];
                hn[uu] = h;
                __nv_bfloat16 hi = __float2bfloat16(h);
                vh[uu] = hi;
                vl[uu] = __float2bfloat16(h - __bfloat162float(hi));
            }
            int off = hsplit_off(b, u0 + uh);         // 8B-aligned start
            *reinterpret_cast<uint2*>(&g_hhi[(t + 1) & 1][off]) =
                *reinterpret_cast<const uint2*>(vh);
            *reinterpret_cast<uint2*>(&g_hlo[(t + 1) & 1][off]) =
                *reinterpret_cast<const uint2*>(vl);
        }
        __syncthreads();

        // ---- per-group grid barrier ----
        if (tid == 0) {
            FENCE_GPU();
            const unsigned tgt = (unsigned)(t + 1);
            unsigned old = atomicAdd(&g_bar4[grp], 1u);
            if (old == (unsigned)GSZ * tgt - 1u) {
                g_flag4[grp] = tgt;
            } else {
                while (g_flag4[grp] < tgt) { }
            }
            FENCE_GPU();
        }
        __syncthreads();
    }
}

// ---------------- weight split prep ----------------
__global__ void prep_kernel(const float* __restrict__ w) {
    int i = blockIdx.x * blockDim.x + threadIdx.x;
    if (i < 3 * DM * DM) {
        float v = w[i];
        __nv_bfloat16 hi = __float2bfloat16(v);
        g_whi[i] = hi;
        g_wlo[i] = __float2bfloat16(v - __bfloat162float(hi));
    }
}

// ---------------- h0 ----------------
__global__ void h0_kernel(const float* __restrict__ z,
                          const float* __restrict__ w,
                          const float* __restrict__ bias) {
    __shared__ float zs[LATENT];
    const int b = blockIdx.x;
    const int j = threadIdx.x;
    if (b == 0 && j < 4) { g_bar4[j] = 0; g_flag4[j] = 0; }   // reset per replay
    if (threadIdx.x < LATENT) zs[threadIdx.x] = z[b * LATENT + threadIdx.x];
    __syncthreads();
    float acc = 0.f;
    const float4* wr = reinterpret_cast<const float4*>(w + (size_t)j * LATENT);
#pragma unroll
    for (int k4 = 0; k4 < LATENT / 4; k4++) {
        float4 w4 = __ldg(&wr[k4]);
        acc += zs[4 * k4 + 0] * w4.x + zs[4 * k4 + 1] * w4.y
             + zs[4 * k4 + 2] * w4.z + zs[4 * k4 + 3] * w4.w;
    }
    float h = tanhf(acc + bias[j]);
    g_hs[(size_t)b * DM + j] = h;
    __nv_bfloat16 hi = __float2bfloat16(h);
    int off = hsplit_off(b, j);
    g_hhi[0][off] = hi;
    g_hlo[0][off] = __float2bfloat16(h - __bfloat162float(hi));
}

// ---------------- output GEMM: 128x64 tile, 8x4 per thread ----------------
#define OKC 32
__global__ void __launch_bounds__(256)
out_kernel(const float* __restrict__ out_w,
           const float* __restrict__ out_b,
           float* __restrict__ out) {
    __shared__ float shH[OKC][132];
    __shared__ float shW[OKC][68];
    const int R0  = blockIdx.x * 128;
    const int tid = threadIdx.x;
    const int tx  = tid & 15;
    const int ty  = tid >> 4;
    const float* __restrict__ hsrc = g_hs + (size_t)BS;

    float acc[8][4] = {};
    for (int k0 = 0; k0 < DM; k0 += OKC) {
#pragma unroll
        for (int p = 0; p < 4; p++) {
            int idx = tid + 256 * p;
            int row = idx >> 3;
            int c4  = (idx & 7) * 4;
            float4 v = *reinterpret_cast<const float4*>(
                &hsrc[(size_t)(R0 + row) * DM + k0 + c4]);
            shH[c4 + 0][row] = v.x; shH[c4 + 1][row] = v.y;
            shH[c4 + 2][row] = v.z; shH[c4 + 3][row] = v.w;
        }
#pragma unroll
        for (int p = 0; p < 2; p++) {
            int idx = tid + 256 * p;
            int i   = idx >> 3;
            int c4  = (idx & 7) * 4;
            float4 v = make_float4(0.f, 0.f, 0.f, 0.f);
            if (i < ENC)
                v = *reinterpret_cast<const float4*>(&out_w[(size_t)i * DM + k0 + c4]);
            shW[c4 + 0][i] = v.x; shW[c4 + 1][i] = v.y;
            shW[c4 + 2][i] = v.z; shW[c4 + 3][i] = v.w;
        }
        __syncthreads();
#pragma unroll
        for (int kk = 0; kk < OKC; kk++) {
            float4 h0 = *reinterpret_cast<const float4*>(&shH[kk][ty * 8]);
            float4 h1 = *reinterpret_cast<const float4*>(&shH[kk][ty * 8 + 4]);
            float4 wv = *reinterpret_cast<const float4*>(&shW[kk][tx * 4]);
            float h[8] = {h0.x, h0.y, h0.z, h0.w, h1.x, h1.y, h1.z, h1.w};
            float w[4] = {wv.x, wv.y, wv.z, wv.w};
#pragma unroll
            for (int rr = 0; rr < 8; rr++)
#pragma unroll
                for (int cc = 0; cc < 4; cc++)
                    acc[rr][cc] += h[rr] * w[cc];
        }
        __syncthreads();
    }
#pragma unroll
    for (int rr = 0; rr < 8; rr++) {
        int R  = R0 + ty * 8 + rr;
        int tt = R >> 8;
        int b  = R & 255;
#pragma unroll
        for (int cc = 0; cc < 4; cc++) {
            int i = tx * 4 + cc;
            if (i < ENC)
                out[((size_t)b * WIN + tt) * ENC + i] = acc[rr][cc] + __ldg(&out_b[i]);
        }
    }
}

// ---------------- launch ----------------
extern "C" void kernel_launch(void* const* d_in, const int* in_sizes, int n_in,
                              void* d_out, int out_size) {
    (void)in_sizes; (void)n_in; (void)out_size;
    const float* z        = (const float*)d_in[0];
    const float* h_proj_w = (const float*)d_in[1];
    const float* h_proj_b = (const float*)d_in[2];
    const float* w_hh     = (const float*)d_in[4];
    const float* b_ih     = (const float*)d_in[5];
    const float* b_hh     = (const float*)d_in[6];
    const float* out_w    = (const float*)d_in[7];
    const float* out_b    = (const float*)d_in[8];
    float* out = (float*)d_out;

    static bool attr_done = false;
    if (!attr_done) {
        cudaFuncSetAttribute(gru_persistent,
                             cudaFuncAttributeMaxDynamicSharedMemorySize, DYN_BYTES);
        attr_done = true;
    }

    prep_kernel<<<(3 * DM * DM + 255) / 256, 256>>>(w_hh);
    h0_kernel<<<BATCH, DM>>>(z, h_proj_w, h_proj_b);
    gru_persistent<<<NCTA, 256, DYN_BYTES>>>(b_ih, b_hh);
    out_kernel<<<(WIN * BATCH) / 128, 256>>>(out_w, out_b, out);
}

// round 8
// speedup vs baseline: 2.0237x; 1.1327x over previous
#include <cuda_runtime.h>
#include <cuda_bf16.h>
#include <cstdint>
#include <math.h>

#define DM     512
#define BATCH  256
#define WIN    256
#define ENC    55
#define LATENT 128
#define BS     (BATCH * DM)

// ---------------- global scratch ----------------
__device__ float g_hs[(WIN + 1) * BS];            // fp32 hidden history (normal layout)
// h split ping-pong, K-CHUNKED swizzled layout:
// off(b,u) = (b>>6)<<15 | (u>>7)<<13 | (b&63)<<7 | ((((u>>3)&15) ^ (b&7))<<3) | (u&7)
__device__ __nv_bfloat16 g_hhi[2][BS];
__device__ __nv_bfloat16 g_hlo[2][BS];
__device__ __nv_bfloat16 g_whi[3 * DM * DM];      // W split hi (normal layout)
__device__ __nv_bfloat16 g_wlo[3 * DM * DM];      // W split lo
__device__ unsigned g_bar4[4];                    // per-group arrival counters
__device__ volatile unsigned g_flag4[4];          // per-group release flags

// ---------------- PTX helpers ----------------
__device__ __forceinline__ uint32_t smem_u32(const void* p) {
    uint32_t a;
    asm("{ .reg .u64 t; cvta.to.shared.u64 t, %1; cvt.u32.u64 %0, t; }" : "=r"(a) : "l"(p));
    return a;
}
__device__ __forceinline__ void bulkcp(uint32_t dst, const void* src, uint32_t bytes,
                                       uint32_t mbar) {
    asm volatile("cp.async.bulk.shared::cluster.global.mbarrier::complete_tx::bytes "
                 "[%0], [%1], %2, [%3];"
                 :: "r"(dst), "l"(src), "r"(bytes), "r"(mbar) : "memory");
}
#define MBAR_INIT(a, c) asm volatile("mbarrier.init.shared.b64 [%0], %1;" :: "r"(a), "r"(c) : "memory")
#define MBAR_EXPECT(a, bytes) \
    asm volatile("mbarrier.arrive.expect_tx.shared.b64 _, [%0], %1;" :: "r"(a), "r"(bytes) : "memory")
#define MBAR_WAIT(a, par) do {                                                              \
    uint32_t _m = (a), _p = (par), _d;                                                      \
    asm volatile("{ .reg .pred p; mbarrier.try_wait.parity.acquire.cta.shared::cta.b64 p, [%1], %2; selp.b32 %0,1,0,p; }" \
                 : "=r"(_d) : "r"(_m), "r"(_p) : "memory");                                 \
    if (!_d) {                                                                              \
        asm volatile("{ .reg .pred P1; WL%=: mbarrier.try_wait.parity.acquire.cta.shared::cta.b64 P1, [%0], %1, 0x989680; @P1 bra.uni WD%=; bra.uni WL%=; WD%=: }" \
                     :: "r"(_m), "r"(_p) : "memory");                                       \
    }                                                                                       \
} while (0)
#define FENCE_ASYNC()  asm volatile("fence.proxy.async;" ::: "memory")
#define FENCE_GPU()    asm volatile("fence.acq_rel.gpu;" ::: "memory")

__device__ __forceinline__ void ldsm_x4(uint32_t r[4], uint32_t addr) {
    asm volatile("ldmatrix.sync.aligned.m8n8.x4.shared.b16 {%0,%1,%2,%3}, [%4];"
                 : "=r"(r[0]), "=r"(r[1]), "=r"(r[2]), "=r"(r[3]) : "r"(addr));
}
__device__ __forceinline__ void ldsm_x2(uint32_t r[2], uint32_t addr) {
    asm volatile("ldmatrix.sync.aligned.m8n8.x2.shared.b16 {%0,%1}, [%2];"
                 : "=r"(r[0]), "=r"(r[1]) : "r"(addr));
}
__device__ __forceinline__ void mma_bf16(float c[4], const uint32_t a[4], const uint32_t b[2]) {
    asm volatile("mma.sync.aligned.m16n8k16.row.col.f32.bf16.bf16.f32 "
                 "{%0,%1,%2,%3}, {%4,%5,%6,%7}, {%8,%9}, {%0,%1,%2,%3};"
                 : "+f"(c[0]), "+f"(c[1]), "+f"(c[2]), "+f"(c[3])
                 : "r"(a[0]), "r"(a[1]), "r"(a[2]), "r"(a[3]), "r"(b[0]), "r"(b[1]));
}
__device__ __forceinline__ float sigf(float x)  { return 1.f / (1.f + __expf(-x)); }
__device__ __forceinline__ float tanhf_fast(float x) {
    float e = __expf(2.f * x);
    return 1.f - 2.f / (e + 1.f);
}

// ---------------- persistent kernel config ----------------
#define NCTA    128
#define UT      16                    // units per CTA (N = 48)
#define MT      64                    // batch rows per CTA
#define GSZ     32                    // CTAs per batch group
// dyn smem layout (bytes):
#define WS_HI   0                     // 48 rows x 1024B, swizzled
#define WS_LO   49152
#define AS_BASE 98304                 // 4 K-chunks x (hi 16KB + lo 16KB)
#define AKCH_B  32768                 // per K-chunk bytes (hi+lo)
#define DYN_BYTES 229376

// split-h elem offset (K-chunked swizzled tiles)
__device__ __forceinline__ int hsplit_off(int b, int u) {
    int r = b & 63;
    return ((b >> 6) << 15) + ((u >> 7) << 13) + (r << 7)
         + ((((u >> 3) & 15) ^ (r & 7)) << 3) + (u & 7);
}

__global__ void __launch_bounds__(256, 1)
gru_persistent(const float* __restrict__ b_ih, const float* __restrict__ b_hh) {
    extern __shared__ char dyn[];
    __shared__ __align__(16) uint64_t s_mbar[4];
    __shared__ float s_sr[UT], s_sz[UT], s_bin[UT], s_bhn[UT];

    const int tid = threadIdx.x;
    const int lane = tid & 31;
    const int warp = tid >> 5;
    const int m_base = (warp >> 1) * 16;    // 4 M-tiles of 16 rows
    const int warp_n = warp & 1;
    const int n_base = warp_n * 24;
    const int cta = blockIdx.x;
    const int u0 = (cta & 31) * UT;
    const int grp = cta >> 5;               // batch group 0..3
    const int gb0 = grp * MT;
    const uint32_t sb = smem_u32(dyn);

    // ---- resident W tiles with gate-unit PERMUTED column order ----
    // smem row n: nb=n/24, rem=n%24, ni=rem/8, r2=rem%8 (=q*2+e), j=ni*2+e
    //   -> unit u = nb*8 + q*2 + j/3, gate g = j%3
    for (int idx = tid; idx < 48 * 64; idx += 256) {
        int n = idx >> 6, g = idx & 63;
        int nb = n / 24, rem = n % 24;
        int ni = rem >> 3, r2 = rem & 7;
        int q = r2 >> 1, e = r2 & 1;
        int j = ni * 2 + e;
        int usel = (j >= 3) ? 1 : 0;
        int gate = j - usel * 3;
        int gr = gate * DM + u0 + nb * 8 + q * 2 + usel;
        int sg = g ^ (n & 7);
        *reinterpret_cast<uint4*>(dyn + WS_HI + n * 1024 + sg * 16) =
            *reinterpret_cast<const uint4*>(g_whi + (size_t)gr * DM + g * 8);
        *reinterpret_cast<uint4*>(dyn + WS_LO + n * 1024 + sg * 16) =
            *reinterpret_cast<const uint4*>(g_wlo + (size_t)gr * DM + g * 8);
    }
    if (tid < UT) {
        int j = u0 + tid;
        s_sr[tid]  = b_ih[j] + b_hh[j];
        s_sz[tid]  = b_ih[DM + j] + b_hh[DM + j];
        s_bin[tid] = b_ih[2 * DM + j];
        s_bhn[tid] = b_hh[2 * DM + j];
    }
    if (tid == 0) {
        uint32_t mb = smem_u32(s_mbar);
#pragma unroll
        for (int i = 0; i < 4; i++) MBAR_INIT(mb + 8 * i, 1);
        FENCE_ASYNC();
    }
    __syncthreads();
    const uint32_t mb0 = smem_u32(s_mbar);

    // per-lane fragment addressing
    const int arowl = (lane & 7) + ((lane >> 3) & 1) * 8;     // row within m-tile
    const int aHalf = (lane >> 4) & 1;
    const int sA = arowl & 7;
    const uint32_t aBase = sb + AS_BASE + (uint32_t)(m_base + arowl) * 256;
    const int sW = lane & 7;
    const int wHalf = (lane >> 3) & 1;
    const uint32_t wHiBase = sb + WS_HI + (uint32_t)(n_base + (lane & 7)) * 1024;
    const uint32_t wLoBase = wHiBase + (WS_LO - WS_HI);

    // epilogue constants
    const int q = lane & 3;
    const int rlo = lane >> 2;
    const int ul0 = warp_n * 8 + q * 2;     // local unit (even), +1 = odd

    for (int t = 0; t < WIN; t++) {
        // ---- issue K-chunked bulk copies for this step's A tile ----
        if (tid == 0) {
            FENCE_ASYNC();
            const __nv_bfloat16* srcH = g_hhi[t & 1] + (grp << 15);
            const __nv_bfloat16* srcL = g_hlo[t & 1] + (grp << 15);
#pragma unroll
            for (int c = 0; c < 4; c++) MBAR_EXPECT(mb0 + 8 * c, AKCH_B);
#pragma unroll
            for (int c = 0; c < 4; c++) {
                bulkcp(sb + AS_BASE + c * AKCH_B, srcH + c * 8192, 16384, mb0 + 8 * c);
                bulkcp(sb + AS_BASE + c * AKCH_B + 16384, srcL + c * 8192, 16384, mb0 + 8 * c);
            }
        }

        float cf[3][4];
#pragma unroll
        for (int ni = 0; ni < 3; ni++)
#pragma unroll
            for (int qq = 0; qq < 4; qq++) cf[ni][qq] = 0.f;

#pragma unroll
        for (int kc = 0; kc < 4; kc++) {
            MBAR_WAIT(mb0 + 8 * kc, t & 1);
            const uint32_t aC = aBase + (uint32_t)kc * AKCH_B;
#pragma unroll
            for (int kk = 0; kk < 8; kk++) {
                const int cA = kk * 2 + aHalf;
                const uint32_t aAddr = aC + (uint32_t)((cA ^ sA) << 4);
                uint32_t ah[4], al[4];
                ldsm_x4(ah, aAddr);
                ldsm_x4(al, aAddr + 16384);
                const int k16 = kc * 8 + kk;
                const int cW = k16 * 2 + wHalf;
                const uint32_t wOff = (uint32_t)((cW ^ sW) << 4);
                uint32_t bh[3][2], bl[3][2];
#pragma unroll
                for (int ni = 0; ni < 3; ni++) {
                    ldsm_x2(bh[ni], wHiBase + ni * 8192 + wOff);
                    ldsm_x2(bl[ni], wLoBase + ni * 8192 + wOff);
                }
#pragma unroll
                for (int ni = 0; ni < 3; ni++) {
                    mma_bf16(cf[ni], ah, bh[ni]);
                    mma_bf16(cf[ni], ah, bl[ni]);
                    mma_bf16(cf[ni], al, bh[ni]);
                }
            }
        }

        // ---- direct epilogue on fragments (no exchange) ----
        {
            const float bsr0 = s_sr[ul0],      bsr1 = s_sr[ul0 + 1];
            const float bsz0 = s_sz[ul0],      bsz1 = s_sz[ul0 + 1];
            const float bin0 = s_bin[ul0],     bin1 = s_bin[ul0 + 1];
            const float bhn0 = s_bhn[ul0],     bhn1 = s_bhn[ul0 + 1];
#pragma unroll
            for (int hh = 0; hh < 2; hh++) {
                const int b = gb0 + m_base + rlo + hh * 8;
                const float2 hp2 = *reinterpret_cast<const float2*>(
                    &g_hs[(size_t)t * BS + (size_t)b * DM + u0 + ul0]);
                // unit sel 0: gates j=0,1,2 ; unit sel 1: gates j=3,4,5
                float gr0 = cf[0][hh * 2 + 0], gz0 = cf[0][hh * 2 + 1], gn0 = cf[1][hh * 2 + 0];
                float gr1 = cf[1][hh * 2 + 1], gz1 = cf[2][hh * 2 + 0], gn1 = cf[2][hh * 2 + 1];
                float r0v = sigf(bsr0 + gr0);
                float z0v = sigf(bsz0 + gz0);
                float n0v = tanhf_fast(bin0 + r0v * (bhn0 + gn0));
                float h0v = (1.f - z0v) * n0v + z0v * hp2.x;
                float r1v = sigf(bsr1 + gr1);
                float z1v = sigf(bsz1 + gz1);
                float n1v = tanhf_fast(bin1 + r1v * (bhn1 + gn1));
                float h1v = (1.f - z1v) * n1v + z1v * hp2.y;
                *reinterpret_cast<float2*>(
                    &g_hs[(size_t)(t + 1) * BS + (size_t)b * DM + u0 + ul0]) =
                    make_float2(h0v, h1v);
                __nv_bfloat16 hi0 = __float2bfloat16(h0v);
                __nv_bfloat16 hi1 = __float2bfloat16(h1v);
                __nv_bfloat16 lo0 = __float2bfloat16(h0v - __bfloat162float(hi0));
                __nv_bfloat16 lo1 = __float2bfloat16(h1v - __bfloat162float(hi1));
                int off = hsplit_off(b, u0 + ul0);
                __nv_bfloat162 vh; vh.x = hi0; vh.y = hi1;
                __nv_bfloat162 vl; vl.x = lo0; vl.y = lo1;
                *reinterpret_cast<__nv_bfloat162*>(&g_hhi[(t + 1) & 1][off]) = vh;
                *reinterpret_cast<__nv_bfloat162*>(&g_hlo[(t + 1) & 1][off]) = vl;
            }
        }
        __syncthreads();

        // ---- per-group grid barrier ----
        if (tid == 0) {
            FENCE_GPU();
            const unsigned tgt = (unsigned)(t + 1);
            unsigned old = atomicAdd(&g_bar4[grp], 1u);
            if (old == (unsigned)GSZ * tgt - 1u) {
                g_flag4[grp] = tgt;
            } else {
                while (g_flag4[grp] < tgt) { }
            }
            FENCE_GPU();
        }
        __syncthreads();
    }
}

// ---------------- weight split prep ----------------
__global__ void prep_kernel(const float* __restrict__ w) {
    int i = blockIdx.x * blockDim.x + threadIdx.x;
    if (i < 3 * DM * DM) {
        float v = w[i];
        __nv_bfloat16 hi = __float2bfloat16(v);
        g_whi[i] = hi;
        g_wlo[i] = __float2bfloat16(v - __bfloat162float(hi));
    }
}

// ---------------- h0 ----------------
__global__ void h0_kernel(const float* __restrict__ z,
                          const float* __restrict__ w,
                          const float* __restrict__ bias) {
    __shared__ float zs[LATENT];
    const int b = blockIdx.x;
    const int j = threadIdx.x;
    if (b == 0 && j < 4) { g_bar4[j] = 0; g_flag4[j] = 0; }   // reset per replay
    if (threadIdx.x < LATENT) zs[threadIdx.x] = z[b * LATENT + threadIdx.x];
    __syncthreads();
    float acc = 0.f;
    const float4* wr = reinterpret_cast<const float4*>(w + (size_t)j * LATENT);
#pragma unroll
    for (int k4 = 0; k4 < LATENT / 4; k4++) {
        float4 w4 = __ldg(&wr[k4]);
        acc += zs[4 * k4 + 0] * w4.x + zs[4 * k4 + 1] * w4.y
             + zs[4 * k4 + 2] * w4.z + zs[4 * k4 + 3] * w4.w;
    }
    float h = tanhf(acc + bias[j]);
    g_hs[(size_t)b * DM + j] = h;
    __nv_bfloat16 hi = __float2bfloat16(h);
    int off = hsplit_off(b, j);
    g_hhi[0][off] = hi;
    g_hlo[0][off] = __float2bfloat16(h - __bfloat162float(hi));
}

// ---------------- output GEMM: 128x64 tile, 8x4 per thread (proven) ----------------
#define OKC 32
__global__ void __launch_bounds__(256)
out_kernel(const float* __restrict__ out_w,
           const float* __restrict__ out_b,
           float* __restrict__ out) {
    __shared__ float shH[OKC][132];
    __shared__ float shW[OKC][68];
    const int R0  = blockIdx.x * 128;
    const int tid = threadIdx.x;
    const int tx  = tid & 15;
    const int ty  = tid >> 4;
    const float* __restrict__ hsrc = g_hs + (size_t)BS;

    float acc[8][4] = {};
    for (int k0 = 0; k0 < DM; k0 += OKC) {
#pragma unroll
        for (int p = 0; p < 4; p++) {
            int idx = tid + 256 * p;
            int row = idx >> 3;
            int c4  = (idx & 7) * 4;
            float4 v = *reinterpret_cast<const float4*>(
                &hsrc[(size_t)(R0 + row) * DM + k0 + c4]);
            shH[c4 + 0][row] = v.x; shH[c4 + 1][row] = v.y;
            shH[c4 + 2][row] = v.z; shH[c4 + 3][row] = v.w;
        }
#pragma unroll
        for (int p = 0; p < 2; p++) {
            int idx = tid + 256 * p;
            int i   = idx >> 3;
            int c4  = (idx & 7) * 4;
            float4 v = make_float4(0.f, 0.f, 0.f, 0.f);
            if (i < ENC)
                v = *reinterpret_cast<const float4*>(&out_w[(size_t)i * DM + k0 + c4]);
            shW[c4 + 0][i] = v.x; shW[c4 + 1][i] = v.y;
            shW[c4 + 2][i] = v.z; shW[c4 + 3][i] = v.w;
        }
        __syncthreads();
#pragma unroll
        for (int kk = 0; kk < OKC; kk++) {
            float4 h0 = *reinterpret_cast<const float4*>(&shH[kk][ty * 8]);
            float4 h1 = *reinterpret_cast<const float4*>(&shH[kk][ty * 8 + 4]);
            float4 wv = *reinterpret_cast<const float4*>(&shW[kk][tx * 4]);
            float h[8] = {h0.x, h0.y, h0.z, h0.w, h1.x, h1.y, h1.z, h1.w};
            float w[4] = {wv.x, wv.y, wv.z, wv.w};
#pragma unroll
            for (int rr = 0; rr < 8; rr++)
#pragma unroll
                for (int cc = 0; cc < 4; cc++)
                    acc[rr][cc] += h[rr] * w[cc];
        }
        __syncthreads();
    }
#pragma unroll
    for (int rr = 0; rr < 8; rr++) {
        int R  = R0 + ty * 8 + rr;
        int tt = R >> 8;
        int b  = R & 255;
#pragma unroll
        for (int cc = 0; cc < 4; cc++) {
            int i = tx * 4 + cc;
            if (i < ENC)
                out[((size_t)b * WIN + tt) * ENC + i] = acc[rr][cc] + __ldg(&out_b[i]);
        }
    }
}

// ---------------- launch ----------------
extern "C" void kernel_launch(void* const* d_in, const int* in_sizes, int n_in,
                              void* d_out, int out_size) {
    (void)in_sizes; (void)n_in; (void)out_size;
    const float* z        = (const float*)d_in[0];
    const float* h_proj_w = (const float*)d_in[1];
    const float* h_proj_b = (const float*)d_in[2];
    const float* w_hh     = (const float*)d_in[4];
    const float* b_ih     = (const float*)d_in[5];
    const float* b_hh     = (const float*)d_in[6];
    const float* out_w    = (const float*)d_in[7];
    const float* out_b    = (const float*)d_in[8];
    float* out = (float*)d_out;

    static bool attr_done = false;
    if (!attr_done) {
        cudaFuncSetAttribute(gru_persistent,
                             cudaFuncAttributeMaxDynamicSharedMemorySize, DYN_BYTES);
        attr_done = true;
    }

    prep_kernel<<<(3 * DM * DM + 255) / 256, 256>>>(w_hh);
    h0_kernel<<<BATCH, DM>>>(z, h_proj_w, h_proj_b);
    gru_persistent<<<NCTA, 256, DYN_BYTES>>>(b_ih, b_hh);
    out_kernel<<<(WIN * BATCH) / 128, 256>>>(out_w, out_b, out);
}